// round 1
// baseline (speedup 1.0000x reference)
#include <cuda_runtime.h>
#include <math.h>

#define NT 50000
#define NP 256
#define NE 800000
#define EMB 64
#define H 4
#define HE 256       // H*EMB
#define NL 3
#define EDIM 8
#define TDIM 16
#define PDIM 8
#define NG 8

// ---------------- scratch (static __device__, no allocs) ----------------
__device__ float g_xl[(size_t)NT * HE];       // per-layer transformed feats
__device__ float g_gout[(size_t)NT * HE];     // GAT aggregation output
__device__ float g_ht[(size_t)NT * EMB];      // node state
__device__ float g_hp[NP * EMB];
__device__ float g_asrc[NT * H];
__device__ float g_adst[NT * H];
__device__ float g_exbuf[(size_t)NE * H];     // alpha -> ex per CSR edge
__device__ float g_aedgp[(size_t)NE * H];     // a_edg per CSR edge
__device__ float g_eaperm[(size_t)NE * EDIM]; // edge_attr permuted to CSR order
__device__ int   g_permsrc[NE];
__device__ int   g_rowptr[NT + 1];
__device__ int   g_deg[NT];
__device__ int   g_off[NT];
__device__ float g_meanea[EDIM];
__device__ float g_c[NL * EDIM * H];          // c[l][j][h]
__device__ float g_loopae[NL * H];            // self-loop a_edg per layer/head
__device__ float g_tp[NG * EMB];
__device__ float g_pp[NG * EMB];
__device__ int   g_cntt[NG];
__device__ int   g_cntp[NG];

// ---------------- init ----------------
__global__ void k_init() {
    int i = blockIdx.x * blockDim.x + threadIdx.x;
    int stride = gridDim.x * blockDim.x;
    for (int k = i; k < NT; k += stride) g_deg[k] = 0;
    if (i < EDIM) g_meanea[i] = 0.f;
    if (i < NG) { g_cntt[i] = 0; g_cntp[i] = 0; }
    for (int k = i; k < NG * EMB; k += stride) { g_tp[k] = 0.f; g_pp[k] = 0.f; }
}

// ---------------- mean of edge_attr ----------------
__global__ void k_meanea(const float* __restrict__ ea) {
    int i = blockIdx.x * blockDim.x + threadIdx.x;
    int stride = gridDim.x * blockDim.x;
    float acc[8] = {0, 0, 0, 0, 0, 0, 0, 0};
    for (int e = i; e < NE; e += stride) {
        const float4* p = (const float4*)(ea + (size_t)e * 8);
        float4 a0 = p[0], a1 = p[1];
        acc[0] += a0.x; acc[1] += a0.y; acc[2] += a0.z; acc[3] += a0.w;
        acc[4] += a1.x; acc[5] += a1.y; acc[6] += a1.z; acc[7] += a1.w;
    }
#pragma unroll
    for (int k = 0; k < 8; k++)
#pragma unroll
        for (int off = 16; off >= 1; off >>= 1)
            acc[k] += __shfl_xor_sync(0xffffffffu, acc[k], off);
    if ((threadIdx.x & 31) == 0)
#pragma unroll
        for (int k = 0; k < 8; k++) atomicAdd(&g_meanea[k], acc[k]);
}

// ---------------- CSR build ----------------
__global__ void k_hist(const int* __restrict__ dst) {
    int e = blockIdx.x * blockDim.x + threadIdx.x;
    if (e < NE) atomicAdd(&g_deg[dst[e]], 1);
}

__global__ void k_scan() {
    __shared__ int sm[1024];
    const int ITEMS = 49;  // 1024*49 >= 50000
    int t = threadIdx.x;
    int base = t * ITEMS;
    int s = 0;
    for (int i = 0; i < ITEMS; i++) {
        int idx = base + i;
        if (idx < NT) s += g_deg[idx];
    }
    sm[t] = s;
    __syncthreads();
    for (int off = 1; off < 1024; off <<= 1) {
        int v = (t >= off) ? sm[t - off] : 0;
        __syncthreads();
        sm[t] += v;
        __syncthreads();
    }
    int run = sm[t] - s;  // exclusive
    for (int i = 0; i < ITEMS; i++) {
        int idx = base + i;
        if (idx < NT) {
            g_rowptr[idx] = run;
            g_off[idx] = run;
            run += g_deg[idx];
            if (idx == NT - 1) g_rowptr[NT] = run;
        }
    }
}

__global__ void k_scatter(const int* __restrict__ src, const int* __restrict__ dst,
                          const float* __restrict__ ea) {
    int e = blockIdx.x * blockDim.x + threadIdx.x;
    if (e >= NE) return;
    int d = dst[e];
    int p = atomicAdd(&g_off[d], 1);
    g_permsrc[p] = src[e];
    const float4* sp = (const float4*)(ea + (size_t)e * 8);
    float4 a0 = sp[0], a1 = sp[1];
    float4* dp = (float4*)(g_eaperm + (size_t)p * 8);
    dp[0] = a0; dp[1] = a1;
}

// ---------------- combined edge-attention vectors c[l][j][h] ----------------
__global__ void k_cvec(const float* __restrict__ We, const float* __restrict__ ae) {
    int t = threadIdx.x;
    if (t < NL * EDIM * H) {
        int l = t >> 5; int r = t & 31; int j = r >> 2; int h = r & 3;
        float s = 0.f;
        for (int d = 0; d < EMB; d++)
            s += We[((size_t)(l * EDIM + j)) * HE + h * EMB + d] * ae[(l * H + h) * EMB + d];
        g_c[t] = s;
    }
    __syncthreads();
    if (t < NL * H) {
        int l = t >> 2; int h = t & 3;
        float s = 0.f;
        for (int j = 0; j < EDIM; j++)
            s += (g_meanea[j] * (1.f / NE)) * g_c[l * 32 + j * 4 + h];
        g_loopae[t] = s;
    }
}

// ---------------- input embeds ----------------
__global__ void k_embed_task(const float* __restrict__ x, const float* __restrict__ W,
                             const float* __restrict__ b) {
    __shared__ float sW[TDIM * EMB];
    __shared__ float sb[EMB];
    __shared__ float sx[4][TDIM];
    int tx = threadIdx.x, ty = threadIdx.y;
    int tid = ty * 64 + tx;
    for (int i = tid; i < TDIM * EMB; i += 256) sW[i] = W[i];
    if (tid < EMB) sb[tid] = b[tid];
    int n = blockIdx.x * 4 + ty;
    if (tx < TDIM && n < NT) sx[ty][tx] = x[(size_t)n * TDIM + tx];
    __syncthreads();
    if (n < NT) {
        float a = sb[tx];
#pragma unroll
        for (int k = 0; k < TDIM; k++) a = fmaf(sx[ty][k], sW[k * EMB + tx], a);
        g_ht[(size_t)n * EMB + tx] = a;
    }
}

__global__ void k_embed_proc(const float* __restrict__ x, const float* __restrict__ W,
                             const float* __restrict__ b) {
    int idx = blockIdx.x * blockDim.x + threadIdx.x;
    if (idx >= NP * EMB) return;
    int n = idx >> 6, c = idx & 63;
    float a = b[c];
#pragma unroll
    for (int k = 0; k < PDIM; k++) a = fmaf(__ldg(&x[n * PDIM + k]), __ldg(&W[k * EMB + c]), a);
    g_hp[idx] = a;
}

// ---------------- GEMM1: xl = h_t @ W[l]  ([NT,64]x[64,256]) ----------------
__global__ __launch_bounds__(256) void k_gemm1(const float* __restrict__ B) {
    __shared__ float As[64][65];
    __shared__ float Bs[64][65];
    int tid = threadIdx.x;
    int row0 = blockIdx.x * 64, col0 = blockIdx.y * 64;
#pragma unroll
    for (int i = 0; i < 16; i++) {
        int idx = tid + i * 256;
        int r = idx >> 6, k = idx & 63;
        int rr = row0 + r;
        As[r][k] = (rr < NT) ? g_ht[(size_t)rr * 64 + k] : 0.f;
        Bs[r][k] = B[(size_t)r * HE + col0 + k];  // r = k-index, k = col
    }
    __syncthreads();
    int tx = tid & 15, ty = tid >> 4;
    float acc[4][4] = {};
#pragma unroll
    for (int k = 0; k < 64; k++) {
        float a[4], bb[4];
#pragma unroll
        for (int i = 0; i < 4; i++) a[i] = As[ty * 4 + i][k];
#pragma unroll
        for (int j = 0; j < 4; j++) bb[j] = Bs[k][tx * 4 + j];
#pragma unroll
        for (int i = 0; i < 4; i++)
#pragma unroll
            for (int j = 0; j < 4; j++) acc[i][j] = fmaf(a[i], bb[j], acc[i][j]);
    }
#pragma unroll
    for (int i = 0; i < 4; i++) {
        int r = row0 + ty * 4 + i;
        if (r < NT) {
            float4 v = make_float4(acc[i][0], acc[i][1], acc[i][2], acc[i][3]);
            *(float4*)&g_xl[(size_t)r * HE + col0 + tx * 4] = v;
        }
    }
}

// ---------------- a_src / a_dst per node (warp per node) ----------------
__global__ void k_attdots(const float* __restrict__ as, const float* __restrict__ adv) {
    int warp = blockIdx.x * (blockDim.x >> 5) + (threadIdx.x >> 5);
    if (warp >= NT) return;
    int lane = threadIdx.x & 31;
    int n = warp;
    int h = lane >> 3;
    int c0 = lane * 8;
    const float4* xp = (const float4*)(g_xl + (size_t)n * HE + c0);
    float4 v0 = __ldg(xp), v1 = __ldg(xp + 1);
    float v[8] = {v0.x, v0.y, v0.z, v0.w, v1.x, v1.y, v1.z, v1.w};
    float ps = 0.f, pd = 0.f;
    int dbase = (lane & 7) * 8;
#pragma unroll
    for (int j = 0; j < 8; j++) {
        ps = fmaf(v[j], __ldg(&as[h * EMB + dbase + j]), ps);
        pd = fmaf(v[j], __ldg(&adv[h * EMB + dbase + j]), pd);
    }
#pragma unroll
    for (int off = 4; off >= 1; off >>= 1) {
        ps += __shfl_xor_sync(0xffffffffu, ps, off);
        pd += __shfl_xor_sync(0xffffffffu, pd, off);
    }
    if ((lane & 7) == 0) {
        g_asrc[n * 4 + h] = ps;
        g_adst[n * 4 + h] = pd;
    }
}

// ---------------- a_edg per CSR edge ----------------
__global__ void k_aedgp(int layer) {
    int e = blockIdx.x * blockDim.x + threadIdx.x;
    if (e >= NE) return;
    const float4* p = (const float4*)(g_eaperm + (size_t)e * 8);
    float4 a0 = p[0], a1 = p[1];
    float ea[8] = {a0.x, a0.y, a0.z, a0.w, a1.x, a1.y, a1.z, a1.w};
    const float* cl = g_c + layer * 32;
    float o[4];
#pragma unroll
    for (int h = 0; h < 4; h++) {
        float s = 0.f;
#pragma unroll
        for (int j = 0; j < 8; j++) s = fmaf(ea[j], cl[j * 4 + h], s);
        o[h] = s;
    }
    *(float4*)&g_aedgp[(size_t)e * 4] = make_float4(o[0], o[1], o[2], o[3]);
}

// ---------------- attention softmax + aggregate (warp per dst node) ----------------
__global__ __launch_bounds__(128) void k_agg(const float* __restrict__ gatb, int layer) {
    int warp = blockIdx.x * 4 + (threadIdx.x >> 5);
    if (warp >= NT) return;
    int lane = threadIdx.x & 31;
    int n = warp;
    int beg = g_rowptr[n], end = g_rowptr[n + 1];
    float4 t;
    t = *(const float4*)&g_adst[n * 4];
    float ad[4] = {t.x, t.y, t.z, t.w};
    t = *(const float4*)&g_asrc[n * 4];
    float an[4] = {t.x, t.y, t.z, t.w};
    const float* lp = g_loopae + layer * 4;
    float la[4], mx[4];
#pragma unroll
    for (int h = 0; h < 4; h++) {
        float v = an[h] + ad[h] + lp[h];
        la[h] = v > 0.f ? v : 0.2f * v;
        mx[h] = la[h];
    }
    // pass 1: alpha + max
    for (int e = beg + lane; e < end; e += 32) {
        int s = g_permsrc[e];
        float4 a4 = *(const float4*)&g_asrc[s * 4];
        float4 e4 = *(const float4*)&g_aedgp[(size_t)e * 4];
        float as4[4] = {a4.x, a4.y, a4.z, a4.w};
        float ae4[4] = {e4.x, e4.y, e4.z, e4.w};
        float al[4];
#pragma unroll
        for (int h = 0; h < 4; h++) {
            float v = as4[h] + ad[h] + ae4[h];
            v = v > 0.f ? v : 0.2f * v;
            al[h] = v;
            mx[h] = fmaxf(mx[h], v);
        }
        *(float4*)&g_exbuf[(size_t)e * 4] = make_float4(al[0], al[1], al[2], al[3]);
    }
#pragma unroll
    for (int off = 16; off >= 1; off >>= 1)
#pragma unroll
        for (int h = 0; h < 4; h++) mx[h] = fmaxf(mx[h], __shfl_xor_sync(0xffffffffu, mx[h], off));
    // pass 2: exp + denom
    float lex[4], dn[4];
#pragma unroll
    for (int h = 0; h < 4; h++) {
        lex[h] = expf(la[h] - mx[h]);
        dn[h] = (lane == 0) ? lex[h] : 0.f;
    }
    for (int e = beg + lane; e < end; e += 32) {
        float4 a4 = *(const float4*)&g_exbuf[(size_t)e * 4];
        float al[4] = {a4.x, a4.y, a4.z, a4.w};
        float ex[4];
#pragma unroll
        for (int h = 0; h < 4; h++) {
            ex[h] = expf(al[h] - mx[h]);
            dn[h] += ex[h];
        }
        *(float4*)&g_exbuf[(size_t)e * 4] = make_float4(ex[0], ex[1], ex[2], ex[3]);
    }
#pragma unroll
    for (int off = 16; off >= 1; off >>= 1)
#pragma unroll
        for (int h = 0; h < 4; h++) dn[h] += __shfl_xor_sync(0xffffffffu, dn[h], off);
    float rc[4];
#pragma unroll
    for (int h = 0; h < 4; h++) rc[h] = 1.f / (dn[h] + 1e-16f);
    int hh = lane >> 3;
    float myrc = hh == 0 ? rc[0] : hh == 1 ? rc[1] : hh == 2 ? rc[2] : rc[3];
    float mylex = hh == 0 ? lex[0] : hh == 1 ? lex[1] : hh == 2 ? lex[2] : lex[3];
    __syncwarp();
    // pass 3: aggregate
    int c0 = lane * 8;
    float acc[8];
    {
        const float4* bp = (const float4*)(gatb + c0);
        float4 b0 = __ldg(bp), b1 = __ldg(bp + 1);
        acc[0] = b0.x; acc[1] = b0.y; acc[2] = b0.z; acc[3] = b0.w;
        acc[4] = b1.x; acc[5] = b1.y; acc[6] = b1.z; acc[7] = b1.w;
    }
    {   // self loop
        float co = mylex * myrc;
        const float4* xp = (const float4*)(g_xl + (size_t)n * HE + c0);
        float4 u0 = __ldg(xp), u1 = __ldg(xp + 1);
        acc[0] = fmaf(co, u0.x, acc[0]); acc[1] = fmaf(co, u0.y, acc[1]);
        acc[2] = fmaf(co, u0.z, acc[2]); acc[3] = fmaf(co, u0.w, acc[3]);
        acc[4] = fmaf(co, u1.x, acc[4]); acc[5] = fmaf(co, u1.y, acc[5]);
        acc[6] = fmaf(co, u1.z, acc[6]); acc[7] = fmaf(co, u1.w, acc[7]);
    }
    for (int e = beg; e < end; e++) {
        int s = g_permsrc[e];
        float ex = __ldg(&g_exbuf[(size_t)e * 4 + hh]);
        float co = ex * myrc;
        const float4* xp = (const float4*)(g_xl + (size_t)s * HE + c0);
        float4 u0 = __ldg(xp), u1 = __ldg(xp + 1);
        acc[0] = fmaf(co, u0.x, acc[0]); acc[1] = fmaf(co, u0.y, acc[1]);
        acc[2] = fmaf(co, u0.z, acc[2]); acc[3] = fmaf(co, u0.w, acc[3]);
        acc[4] = fmaf(co, u1.x, acc[4]); acc[5] = fmaf(co, u1.y, acc[5]);
        acc[6] = fmaf(co, u1.z, acc[6]); acc[7] = fmaf(co, u1.w, acc[7]);
    }
    float4* op = (float4*)(g_gout + (size_t)n * HE + c0);
    op[0] = make_float4(acc[0], acc[1], acc[2], acc[3]);
    op[1] = make_float4(acc[4], acc[5], acc[6], acc[7]);
}

// ---------------- proj GEMM + elu + residual + LN (fused) ----------------
__global__ __launch_bounds__(256) void k_proj_ln(const float* __restrict__ B,
                                                 const float* __restrict__ pb,
                                                 const float* __restrict__ lg,
                                                 const float* __restrict__ lb) {
    __shared__ float As[64][65];
    __shared__ float Bs[64][65];
    __shared__ float r1[64][4], r2[64][4];
    __shared__ float smu[64], srs[64];
    int tid = threadIdx.x;
    int row0 = blockIdx.x * 64;
    int tx = tid & 15, ty = tid >> 4;
    float acc[4][4] = {};
    for (int kt = 0; kt < 4; kt++) {
#pragma unroll
        for (int i = 0; i < 16; i++) {
            int idx = tid + i * 256;
            int r = idx >> 6, k = idx & 63;
            int rr = row0 + r;
            As[r][k] = (rr < NT) ? g_gout[(size_t)rr * HE + kt * 64 + k] : 0.f;
            Bs[r][k] = B[(size_t)(kt * 64 + r) * 64 + k];
        }
        __syncthreads();
#pragma unroll
        for (int k = 0; k < 64; k++) {
            float a[4], bb[4];
#pragma unroll
            for (int i = 0; i < 4; i++) a[i] = As[ty * 4 + i][k];
#pragma unroll
            for (int j = 0; j < 4; j++) bb[j] = Bs[k][tx * 4 + j];
#pragma unroll
            for (int i = 0; i < 4; i++)
#pragma unroll
                for (int j = 0; j < 4; j++) acc[i][j] = fmaf(a[i], bb[j], acc[i][j]);
        }
        __syncthreads();
    }
    // stage upd = elu(acc + bias) into As
#pragma unroll
    for (int i = 0; i < 4; i++)
#pragma unroll
        for (int j = 0; j < 4; j++) {
            int c = tx * 4 + j;
            float u = acc[i][j] + pb[c];
            As[ty * 4 + i][c] = (u > 0.f) ? u : expm1f(u);
        }
    __syncthreads();
    // residual + row stats (4 threads per row, 16 cols each)
    {
        int row = tid >> 2, seg = tid & 3;
        int gr = row0 + row;
        bool valid = gr < NT;
        float s1 = 0.f, s2 = 0.f;
#pragma unroll
        for (int k = 0; k < 16; k++) {
            int c = seg * 16 + k;
            float hres = As[row][c] + (valid ? g_ht[(size_t)gr * 64 + c] : 0.f);
            As[row][c] = hres;
            s1 += hres;
            s2 += hres * hres;
        }
        r1[row][seg] = s1;
        r2[row][seg] = s2;
    }
    __syncthreads();
    if (tid < 64) {
        float mu = (r1[tid][0] + r1[tid][1] + r1[tid][2] + r1[tid][3]) * (1.f / 64.f);
        float ms = (r2[tid][0] + r2[tid][1] + r2[tid][2] + r2[tid][3]) * (1.f / 64.f);
        float var = ms - mu * mu;
        smu[tid] = mu;
        srs[tid] = rsqrtf(var + 1e-5f);
    }
    __syncthreads();
#pragma unroll
    for (int i = 0; i < 16; i++) {
        int idx = tid + i * 256;
        int r = idx >> 6, c = idx & 63;
        int gr = row0 + r;
        if (gr < NT)
            g_ht[(size_t)gr * 64 + c] = (As[r][c] - smu[r]) * srs[r] * __ldg(&lg[c]) + __ldg(&lb[c]);
    }
}

// ---------------- task head ----------------
__global__ __launch_bounds__(256) void k_taskhead(const float* __restrict__ W1,
                                                  const float* __restrict__ b1,
                                                  const float* __restrict__ W2,
                                                  const float* __restrict__ b2,
                                                  float* __restrict__ out) {
    __shared__ float sW1[64 * 32];
    __shared__ float sW2[32];
    __shared__ float sb1[32];
    int tid = threadIdx.x;
    for (int i = tid; i < 64 * 32; i += 256) sW1[i] = W1[i];
    if (tid < 32) { sW2[tid] = W2[tid]; sb1[tid] = b1[tid]; }
    __syncthreads();
    int n = blockIdx.x * 256 + tid;
    if (n >= NT) return;
    float row[64];
    const float4* rp = (const float4*)(g_ht + (size_t)n * 64);
#pragma unroll
    for (int i = 0; i < 16; i++) {
        float4 v = __ldg(rp + i);
        row[i * 4] = v.x; row[i * 4 + 1] = v.y; row[i * 4 + 2] = v.z; row[i * 4 + 3] = v.w;
    }
    float hid[32];
#pragma unroll
    for (int j = 0; j < 32; j++) hid[j] = sb1[j];
#pragma unroll 4
    for (int k = 0; k < 64; k++) {
        float rv = row[k];
#pragma unroll
        for (int j = 0; j < 32; j++) hid[j] = fmaf(rv, sW1[k * 32 + j], hid[j]);
    }
    float logit = __ldg(b2);
#pragma unroll
    for (int j = 0; j < 32; j++) logit = fmaf(fmaxf(hid[j], 0.f), sW2[j], logit);
    out[n] = logit;
}

// ---------------- pooling ----------------
__global__ void k_pool_task(const int* __restrict__ batch) {
    int c = threadIdx.x;
    int r0 = blockIdx.x * 512;
    int r1 = min(r0 + 512, NT);
    float acc = 0.f; int cg = -1; int cnt = 0;
    for (int r = r0; r < r1; r++) {
        int g = batch[r];
        if (g != cg) {
            if (cg >= 0) {
                atomicAdd(&g_tp[cg * 64 + c], acc);
                if (c == 0) atomicAdd(&g_cntt[cg], cnt);
            }
            cg = g; acc = 0.f; cnt = 0;
        }
        acc += g_ht[(size_t)r * 64 + c];
        cnt++;
    }
    if (cg >= 0) {
        atomicAdd(&g_tp[cg * 64 + c], acc);
        if (c == 0) atomicAdd(&g_cntt[cg], cnt);
    }
}

__global__ void k_pool_proc(const int* __restrict__ batch) {
    int c = threadIdx.x;
    float acc = 0.f; int cg = -1; int cnt = 0;
    for (int r = 0; r < NP; r++) {
        int g = batch[r];
        if (g != cg) {
            if (cg >= 0) {
                atomicAdd(&g_pp[cg * 64 + c], acc);
                if (c == 0) atomicAdd(&g_cntp[cg], cnt);
            }
            cg = g; acc = 0.f; cnt = 0;
        }
        acc += g_hp[r * 64 + c];
        cnt++;
    }
    if (cg >= 0) {
        atomicAdd(&g_pp[cg * 64 + c], acc);
        if (c == 0) atomicAdd(&g_cntp[cg], cnt);
    }
}

// ---------------- value head ----------------
__global__ void k_value(const float* __restrict__ W1, const float* __restrict__ b1,
                        const float* __restrict__ W2, const float* __restrict__ b2,
                        float* __restrict__ out) {
    __shared__ float ge[NG * 128];
    __shared__ float red[512];
    int t = threadIdx.x;
    for (int idx = t; idx < NG * 128; idx += 512) {
        int g = idx >> 7, k = idx & 127;
        float v;
        if (k < 64) v = g_tp[g * 64 + k] / fmaxf((float)g_cntt[g], 1.f);
        else        v = g_pp[g * 64 + (k - 64)] / fmaxf((float)g_cntp[g], 1.f);
        ge[idx] = v;
    }
    __syncthreads();
    int g = t >> 6, j = t & 63;
    float a = b1[j];
#pragma unroll 4
    for (int k = 0; k < 128; k++) a = fmaf(ge[g * 128 + k], W1[k * 64 + j], a);
    red[t] = fmaxf(a, 0.f) * W2[j];
    __syncthreads();
#pragma unroll
    for (int off = 32; off >= 1; off >>= 1) {
        if (j < off) red[t] += red[t + off];
        __syncthreads();
    }
    if (j == 0) out[NT + g] = red[t] + b2[0];
}

// ---------------- copy state outputs ----------------
__global__ void k_copyout(float* __restrict__ out) {
    int i = blockIdx.x * blockDim.x + threadIdx.x;
    int stride = gridDim.x * blockDim.x;
    const int OFF_HT = NT + NG;               // 50008
    const int OFF_HP = OFF_HT + NT * EMB;     // 3250008
    for (int k = i; k < NT * EMB; k += stride) out[OFF_HT + k] = g_ht[k];
    for (int k = i; k < NP * EMB; k += stride) out[OFF_HP + k] = g_hp[k];
}

// ---------------- launch ----------------
extern "C" void kernel_launch(void* const* d_in, const int* in_sizes, int n_in,
                              void* d_out, int out_size) {
    const float *x_task, *x_proc, *edge_attr, *W_task, *b_task, *W_proc, *b_proc;
    const float *gat_W, *gat_We, *att_src, *att_dst, *att_edge, *gat_b, *proj_W, *proj_b;
    const float *ln_g, *ln_b, *pt_W1, *pt_b1, *pt_W2, *pt_b2, *v_W1, *v_b1, *v_W2, *v_b2;
    const int *edge_index, *task_batch, *proc_batch;

    if (in_sizes[2] == 2 * NE) {  // setup_inputs dict order
        x_task = (const float*)d_in[0];  x_proc = (const float*)d_in[1];
        edge_index = (const int*)d_in[2]; edge_attr = (const float*)d_in[3];
        task_batch = (const int*)d_in[4]; proc_batch = (const int*)d_in[5];
        W_task = (const float*)d_in[6];  b_task = (const float*)d_in[7];
        W_proc = (const float*)d_in[8];  b_proc = (const float*)d_in[9];
        gat_W = (const float*)d_in[10];  gat_We = (const float*)d_in[11];
        att_src = (const float*)d_in[12]; att_dst = (const float*)d_in[13];
        att_edge = (const float*)d_in[14]; gat_b = (const float*)d_in[15];
        proj_W = (const float*)d_in[16]; proj_b = (const float*)d_in[17];
        ln_g = (const float*)d_in[18];   ln_b = (const float*)d_in[19];
        pt_W1 = (const float*)d_in[20];  pt_b1 = (const float*)d_in[21];
        pt_W2 = (const float*)d_in[22];  pt_b2 = (const float*)d_in[23];
        v_W1 = (const float*)d_in[24];   v_b1 = (const float*)d_in[25];
        v_W2 = (const float*)d_in[26];   v_b2 = (const float*)d_in[27];
    } else {  // reference() signature order
        x_task = (const float*)d_in[0];  x_proc = (const float*)d_in[1];
        edge_attr = (const float*)d_in[2];
        W_task = (const float*)d_in[3];  b_task = (const float*)d_in[4];
        W_proc = (const float*)d_in[5];  b_proc = (const float*)d_in[6];
        gat_W = (const float*)d_in[7];   gat_We = (const float*)d_in[8];
        att_src = (const float*)d_in[9]; att_dst = (const float*)d_in[10];
        att_edge = (const float*)d_in[11]; gat_b = (const float*)d_in[12];
        proj_W = (const float*)d_in[13]; proj_b = (const float*)d_in[14];
        ln_g = (const float*)d_in[15];   ln_b = (const float*)d_in[16];
        pt_W1 = (const float*)d_in[17];  pt_b1 = (const float*)d_in[18];
        pt_W2 = (const float*)d_in[19];  pt_b2 = (const float*)d_in[20];
        v_W1 = (const float*)d_in[21];   v_b1 = (const float*)d_in[22];
        v_W2 = (const float*)d_in[23];   v_b2 = (const float*)d_in[24];
        edge_index = (const int*)d_in[25];
        task_batch = (const int*)d_in[26]; proc_batch = (const int*)d_in[27];
    }
    float* out = (float*)d_out;
    const int* e_src = edge_index;
    const int* e_dst = edge_index + NE;

    k_init<<<128, 256>>>();
    k_meanea<<<256, 256>>>(edge_attr);
    k_hist<<<(NE + 255) / 256, 256>>>(e_dst);
    k_scan<<<1, 1024>>>();
    k_scatter<<<(NE + 255) / 256, 256>>>(e_src, e_dst, edge_attr);
    k_cvec<<<1, 128>>>(gat_We, att_edge);
    k_embed_task<<<NT / 4, dim3(64, 4)>>>(x_task, W_task, b_task);
    k_embed_proc<<<(NP * EMB + 255) / 256, 256>>>(x_proc, W_proc, b_proc);

    for (int l = 0; l < NL; l++) {
        k_gemm1<<<dim3((NT + 63) / 64, 4), 256>>>(gat_W + (size_t)l * EMB * HE);
        k_attdots<<<NT / 4, 128>>>(att_src + l * H * EMB, att_dst + l * H * EMB);
        k_aedgp<<<(NE + 255) / 256, 256>>>(l);
        k_agg<<<NT / 4, 128>>>(gat_b + l * HE, l);
        k_proj_ln<<<(NT + 63) / 64, 256>>>(proj_W + (size_t)l * HE * EMB,
                                           proj_b + l * EMB, ln_g + l * EMB, ln_b + l * EMB);
    }

    k_taskhead<<<(NT + 255) / 256, 256>>>(pt_W1, pt_b1, pt_W2, pt_b2, out);
    k_pool_task<<<(NT + 511) / 512, 64>>>(task_batch);
    k_pool_proc<<<1, 64>>>(proc_batch);
    k_value<<<1, 512>>>(v_W1, v_b1, v_W2, v_b2, out);
    k_copyout<<<2048, 256>>>(out);
}

// round 2
// speedup vs baseline: 1.1115x; 1.1115x over previous
#include <cuda_runtime.h>
#include <math.h>

#define NT 50000
#define NP 256
#define NE 800000
#define EMB 64
#define H 4
#define HE 256       // H*EMB
#define NL 3
#define EDIM 8
#define TDIM 16
#define PDIM 8
#define NG 8
#define SCAN_B 196   // ceil(NT/256)

// ---------------- scratch (static __device__, no allocs) ----------------
__device__ float g_xl[(size_t)NT * HE];       // per-layer transformed feats
__device__ float g_gout[(size_t)NT * HE];     // GAT aggregation output
__device__ float g_ht[(size_t)NT * EMB];      // node state
__device__ float g_hp[NP * EMB];
__device__ float g_asrc[NT * H];
__device__ float g_adst[NT * H];
__device__ float g_exbuf[(size_t)NE * H];     // alpha -> ex per CSR edge
__device__ float g_eaperm[(size_t)NE * EDIM]; // edge_attr permuted to CSR order
__device__ int   g_permsrc[NE];
__device__ int   g_rowptr[NT + 1];
__device__ int   g_deg[NT];
__device__ int   g_off[NT];
__device__ int   g_bsum[SCAN_B];
__device__ float g_meanea[EDIM];
__device__ float g_c[NL * EDIM * H];          // c[l][j][h]
__device__ float g_loopae[NL * H];            // self-loop a_edg per layer/head
__device__ float g_tp[NG * EMB];
__device__ float g_pp[NG * EMB];
__device__ int   g_cntt[NG];
__device__ int   g_cntp[NG];

// ---------------- init ----------------
__global__ void k_init() {
    int i = blockIdx.x * blockDim.x + threadIdx.x;
    int stride = gridDim.x * blockDim.x;
    for (int k = i; k < NT; k += stride) g_deg[k] = 0;
    if (i < EDIM) g_meanea[i] = 0.f;
    if (i < NG) { g_cntt[i] = 0; g_cntp[i] = 0; }
    for (int k = i; k < NG * EMB; k += stride) { g_tp[k] = 0.f; g_pp[k] = 0.f; }
}

// ---------------- mean of edge_attr ----------------
__global__ void k_meanea(const float* __restrict__ ea) {
    int i = blockIdx.x * blockDim.x + threadIdx.x;
    int stride = gridDim.x * blockDim.x;
    float acc[8] = {0, 0, 0, 0, 0, 0, 0, 0};
    for (int e = i; e < NE; e += stride) {
        const float4* p = (const float4*)(ea + (size_t)e * 8);
        float4 a0 = p[0], a1 = p[1];
        acc[0] += a0.x; acc[1] += a0.y; acc[2] += a0.z; acc[3] += a0.w;
        acc[4] += a1.x; acc[5] += a1.y; acc[6] += a1.z; acc[7] += a1.w;
    }
#pragma unroll
    for (int k = 0; k < 8; k++)
#pragma unroll
        for (int off = 16; off >= 1; off >>= 1)
            acc[k] += __shfl_xor_sync(0xffffffffu, acc[k], off);
    if ((threadIdx.x & 31) == 0)
#pragma unroll
        for (int k = 0; k < 8; k++) atomicAdd(&g_meanea[k], acc[k]);
}

// ---------------- CSR build ----------------
__global__ void k_hist(const int* __restrict__ dst) {
    int e = blockIdx.x * blockDim.x + threadIdx.x;
    if (e < NE) atomicAdd(&g_deg[dst[e]], 1);
}

// multi-block scan: per-block exclusive scan + block sums
__global__ void k_scan1() {
    __shared__ int sm[256];
    int b = blockIdx.x, t = threadIdx.x;
    int idx = b * 256 + t;
    int v = (idx < NT) ? g_deg[idx] : 0;
    sm[t] = v;
    __syncthreads();
    for (int off = 1; off < 256; off <<= 1) {
        int u = (t >= off) ? sm[t - off] : 0;
        __syncthreads();
        sm[t] += u;
        __syncthreads();
    }
    if (idx < NT) g_rowptr[idx] = sm[t] - v;  // exclusive within block
    if (t == 255) g_bsum[b] = sm[255];
}

__global__ void k_scan2() {
    __shared__ int sm[256];
    int t = threadIdx.x;
    int v = (t < SCAN_B) ? g_bsum[t] : 0;
    sm[t] = v;
    __syncthreads();
    for (int off = 1; off < 256; off <<= 1) {
        int u = (t >= off) ? sm[t - off] : 0;
        __syncthreads();
        sm[t] += u;
        __syncthreads();
    }
    if (t < SCAN_B) g_bsum[t] = sm[t] - v;  // exclusive block offsets
}

__global__ void k_scan3() {
    int idx = blockIdx.x * 256 + threadIdx.x;
    if (idx < NT) {
        int v = g_rowptr[idx] + g_bsum[idx >> 8];
        g_rowptr[idx] = v;
        g_off[idx] = v;
    }
    if (idx == 0) g_rowptr[NT] = NE;
}

__global__ void k_scatter(const int* __restrict__ src, const int* __restrict__ dst,
                          const float* __restrict__ ea) {
    int e = blockIdx.x * blockDim.x + threadIdx.x;
    if (e >= NE) return;
    int d = dst[e];
    int p = atomicAdd(&g_off[d], 1);
    g_permsrc[p] = src[e];
    const float4* sp = (const float4*)(ea + (size_t)e * 8);
    float4 a0 = sp[0], a1 = sp[1];
    float4* dp = (float4*)(g_eaperm + (size_t)p * 8);
    dp[0] = a0; dp[1] = a1;
}

// ---------------- combined edge-attention vectors c[l][j][h] ----------------
__global__ void k_cvec(const float* __restrict__ We, const float* __restrict__ ae) {
    int t = threadIdx.x;
    if (t < NL * EDIM * H) {
        int l = t >> 5; int r = t & 31; int j = r >> 2; int h = r & 3;
        float s = 0.f;
        for (int d = 0; d < EMB; d++)
            s += We[((size_t)(l * EDIM + j)) * HE + h * EMB + d] * ae[(l * H + h) * EMB + d];
        g_c[t] = s;
    }
    __syncthreads();
    if (t < NL * H) {
        int l = t >> 2; int h = t & 3;
        float s = 0.f;
        for (int j = 0; j < EDIM; j++)
            s += (g_meanea[j] * (1.f / NE)) * g_c[l * 32 + j * 4 + h];
        g_loopae[t] = s;
    }
}

// ---------------- input embeds ----------------
__global__ void k_embed_task(const float* __restrict__ x, const float* __restrict__ W,
                             const float* __restrict__ b) {
    __shared__ float sW[TDIM * EMB];
    __shared__ float sb[EMB];
    __shared__ float sx[4][TDIM];
    int tx = threadIdx.x, ty = threadIdx.y;
    int tid = ty * 64 + tx;
    for (int i = tid; i < TDIM * EMB; i += 256) sW[i] = W[i];
    if (tid < EMB) sb[tid] = b[tid];
    int n = blockIdx.x * 4 + ty;
    if (tx < TDIM && n < NT) sx[ty][tx] = x[(size_t)n * TDIM + tx];
    __syncthreads();
    if (n < NT) {
        float a = sb[tx];
#pragma unroll
        for (int k = 0; k < TDIM; k++) a = fmaf(sx[ty][k], sW[k * EMB + tx], a);
        g_ht[(size_t)n * EMB + tx] = a;
    }
}

__global__ void k_embed_proc(const float* __restrict__ x, const float* __restrict__ W,
                             const float* __restrict__ b) {
    int idx = blockIdx.x * blockDim.x + threadIdx.x;
    if (idx >= NP * EMB) return;
    int n = idx >> 6, c = idx & 63;
    float a = b[c];
#pragma unroll
    for (int k = 0; k < PDIM; k++) a = fmaf(__ldg(&x[n * PDIM + k]), __ldg(&W[k * EMB + c]), a);
    g_hp[idx] = a;
}

// ---------------- GEMM1: xl = h_t @ W[l], fused att_src/att_dst dots ----------------
__global__ __launch_bounds__(256) void k_gemm1(const float* __restrict__ B,
                                               const float* __restrict__ as_,
                                               const float* __restrict__ ad_) {
    __shared__ float As[64][65];
    __shared__ float Bs[64][65];
    __shared__ float sas[64], sad[64];
    int tid = threadIdx.x;
    int row0 = blockIdx.x * 64;
    int h = blockIdx.y;          // head index
    int col0 = h * 64;
#pragma unroll
    for (int i = 0; i < 16; i++) {
        int idx = tid + i * 256;
        int r = idx >> 6, k = idx & 63;
        int rr = row0 + r;
        As[r][k] = (rr < NT) ? g_ht[(size_t)rr * 64 + k] : 0.f;
        Bs[r][k] = B[(size_t)r * HE + col0 + k];  // r = k-index, k = col
    }
    if (tid < 64) { sas[tid] = __ldg(&as_[col0 + tid]); sad[tid] = __ldg(&ad_[col0 + tid]); }
    __syncthreads();
    int tx = tid & 15, ty = tid >> 4;
    float acc[4][4] = {};
#pragma unroll
    for (int k = 0; k < 64; k++) {
        float a[4], bb[4];
#pragma unroll
        for (int i = 0; i < 4; i++) a[i] = As[ty * 4 + i][k];
#pragma unroll
        for (int j = 0; j < 4; j++) bb[j] = Bs[k][tx * 4 + j];
#pragma unroll
        for (int i = 0; i < 4; i++)
#pragma unroll
            for (int j = 0; j < 4; j++) acc[i][j] = fmaf(a[i], bb[j], acc[i][j]);
    }
#pragma unroll
    for (int i = 0; i < 4; i++) {
        int r = row0 + ty * 4 + i;
        if (r < NT) {
            float4 v = make_float4(acc[i][0], acc[i][1], acc[i][2], acc[i][3]);
            *(float4*)&g_xl[(size_t)r * HE + col0 + tx * 4] = v;
        }
    }
    // fused attention-dot epilogue: a_src[r,h], a_dst[r,h]
    float ps[4], pd[4];
#pragma unroll
    for (int i = 0; i < 4; i++) {
        float s = 0.f, d = 0.f;
#pragma unroll
        for (int j = 0; j < 4; j++) {
            int c = tx * 4 + j;
            s = fmaf(acc[i][j], sas[c], s);
            d = fmaf(acc[i][j], sad[c], d);
        }
        ps[i] = s; pd[i] = d;
    }
#pragma unroll
    for (int off = 8; off >= 1; off >>= 1)
#pragma unroll
        for (int i = 0; i < 4; i++) {
            ps[i] += __shfl_xor_sync(0xffffffffu, ps[i], off);
            pd[i] += __shfl_xor_sync(0xffffffffu, pd[i], off);
        }
    if (tx == 0) {
#pragma unroll
        for (int i = 0; i < 4; i++) {
            int r = row0 + ty * 4 + i;
            if (r < NT) {
                g_asrc[r * 4 + h] = ps[i];
                g_adst[r * 4 + h] = pd[i];
            }
        }
    }
}

// ---------------- attention softmax + aggregate (warp per dst node) ----------------
// pass1 computes a_edg inline from permuted edge_attr (no separate kernel/buffer)
__global__ __launch_bounds__(128) void k_agg(const float* __restrict__ gatb, int layer) {
    __shared__ float sc[32];
    __shared__ float slp[4];
    if (threadIdx.x < 32) sc[threadIdx.x] = g_c[layer * 32 + threadIdx.x];
    if (threadIdx.x < 4) slp[threadIdx.x] = g_loopae[layer * 4 + threadIdx.x];
    __syncthreads();
    int warp = blockIdx.x * 4 + (threadIdx.x >> 5);
    if (warp >= NT) return;
    int lane = threadIdx.x & 31;
    int n = warp;
    int beg = g_rowptr[n], end = g_rowptr[n + 1];
    float4 t;
    t = *(const float4*)&g_adst[n * 4];
    float ad[4] = {t.x, t.y, t.z, t.w};
    t = *(const float4*)&g_asrc[n * 4];
    float an[4] = {t.x, t.y, t.z, t.w};
    float la[4], mx[4];
#pragma unroll
    for (int h = 0; h < 4; h++) {
        float v = an[h] + ad[h] + slp[h];
        la[h] = v > 0.f ? v : 0.2f * v;
        mx[h] = la[h];
    }
    // pass 1: alpha (incl. inline a_edg) + max
    for (int e = beg + lane; e < end; e += 32) {
        int s = g_permsrc[e];
        float4 a4 = *(const float4*)&g_asrc[s * 4];
        const float4* ep = (const float4*)(g_eaperm + (size_t)e * 8);
        float4 e0 = ep[0], e1 = ep[1];
        float ea[8] = {e0.x, e0.y, e0.z, e0.w, e1.x, e1.y, e1.z, e1.w};
        float as4[4] = {a4.x, a4.y, a4.z, a4.w};
        float al[4];
#pragma unroll
        for (int h = 0; h < 4; h++) {
            float ae = 0.f;
#pragma unroll
            for (int j = 0; j < 8; j++) ae = fmaf(ea[j], sc[j * 4 + h], ae);
            float v = as4[h] + ad[h] + ae;
            v = v > 0.f ? v : 0.2f * v;
            al[h] = v;
            mx[h] = fmaxf(mx[h], v);
        }
        *(float4*)&g_exbuf[(size_t)e * 4] = make_float4(al[0], al[1], al[2], al[3]);
    }
#pragma unroll
    for (int off = 16; off >= 1; off >>= 1)
#pragma unroll
        for (int h = 0; h < 4; h++) mx[h] = fmaxf(mx[h], __shfl_xor_sync(0xffffffffu, mx[h], off));
    // pass 2: exp + denom
    float lex[4], dn[4];
#pragma unroll
    for (int h = 0; h < 4; h++) {
        lex[h] = expf(la[h] - mx[h]);
        dn[h] = (lane == 0) ? lex[h] : 0.f;
    }
    for (int e = beg + lane; e < end; e += 32) {
        float4 a4 = *(const float4*)&g_exbuf[(size_t)e * 4];
        float al[4] = {a4.x, a4.y, a4.z, a4.w};
        float ex[4];
#pragma unroll
        for (int h = 0; h < 4; h++) {
            ex[h] = expf(al[h] - mx[h]);
            dn[h] += ex[h];
        }
        *(float4*)&g_exbuf[(size_t)e * 4] = make_float4(ex[0], ex[1], ex[2], ex[3]);
    }
#pragma unroll
    for (int off = 16; off >= 1; off >>= 1)
#pragma unroll
        for (int h = 0; h < 4; h++) dn[h] += __shfl_xor_sync(0xffffffffu, dn[h], off);
    float rc[4];
#pragma unroll
    for (int h = 0; h < 4; h++) rc[h] = 1.f / (dn[h] + 1e-16f);
    int hh = lane >> 3;
    float myrc = hh == 0 ? rc[0] : hh == 1 ? rc[1] : hh == 2 ? rc[2] : rc[3];
    float mylex = hh == 0 ? lex[0] : hh == 1 ? lex[1] : hh == 2 ? lex[2] : lex[3];
    __syncwarp();
    // pass 3: aggregate
    int c0 = lane * 8;
    float acc[8];
    {
        const float4* bp = (const float4*)(gatb + c0);
        float4 b0 = __ldg(bp), b1 = __ldg(bp + 1);
        acc[0] = b0.x; acc[1] = b0.y; acc[2] = b0.z; acc[3] = b0.w;
        acc[4] = b1.x; acc[5] = b1.y; acc[6] = b1.z; acc[7] = b1.w;
    }
    {   // self loop
        float co = mylex * myrc;
        const float4* xp = (const float4*)(g_xl + (size_t)n * HE + c0);
        float4 u0 = __ldg(xp), u1 = __ldg(xp + 1);
        acc[0] = fmaf(co, u0.x, acc[0]); acc[1] = fmaf(co, u0.y, acc[1]);
        acc[2] = fmaf(co, u0.z, acc[2]); acc[3] = fmaf(co, u0.w, acc[3]);
        acc[4] = fmaf(co, u1.x, acc[4]); acc[5] = fmaf(co, u1.y, acc[5]);
        acc[6] = fmaf(co, u1.z, acc[6]); acc[7] = fmaf(co, u1.w, acc[7]);
    }
    int e = beg;
    for (; e + 2 <= end; e += 2) {
        int s0 = g_permsrc[e];
        int s1 = g_permsrc[e + 1];
        float ex0 = __ldg(&g_exbuf[(size_t)e * 4 + hh]);
        float ex1 = __ldg(&g_exbuf[(size_t)(e + 1) * 4 + hh]);
        const float4* xp0 = (const float4*)(g_xl + (size_t)s0 * HE + c0);
        const float4* xp1 = (const float4*)(g_xl + (size_t)s1 * HE + c0);
        float4 u0 = __ldg(xp0), u1 = __ldg(xp0 + 1);
        float4 v0 = __ldg(xp1), v1 = __ldg(xp1 + 1);
        float co0 = ex0 * myrc, co1 = ex1 * myrc;
        acc[0] = fmaf(co0, u0.x, acc[0]); acc[1] = fmaf(co0, u0.y, acc[1]);
        acc[2] = fmaf(co0, u0.z, acc[2]); acc[3] = fmaf(co0, u0.w, acc[3]);
        acc[4] = fmaf(co0, u1.x, acc[4]); acc[5] = fmaf(co0, u1.y, acc[5]);
        acc[6] = fmaf(co0, u1.z, acc[6]); acc[7] = fmaf(co0, u1.w, acc[7]);
        acc[0] = fmaf(co1, v0.x, acc[0]); acc[1] = fmaf(co1, v0.y, acc[1]);
        acc[2] = fmaf(co1, v0.z, acc[2]); acc[3] = fmaf(co1, v0.w, acc[3]);
        acc[4] = fmaf(co1, v1.x, acc[4]); acc[5] = fmaf(co1, v1.y, acc[5]);
        acc[6] = fmaf(co1, v1.z, acc[6]); acc[7] = fmaf(co1, v1.w, acc[7]);
    }
    for (; e < end; e++) {
        int s = g_permsrc[e];
        float ex = __ldg(&g_exbuf[(size_t)e * 4 + hh]);
        float co = ex * myrc;
        const float4* xp = (const float4*)(g_xl + (size_t)s * HE + c0);
        float4 u0 = __ldg(xp), u1 = __ldg(xp + 1);
        acc[0] = fmaf(co, u0.x, acc[0]); acc[1] = fmaf(co, u0.y, acc[1]);
        acc[2] = fmaf(co, u0.z, acc[2]); acc[3] = fmaf(co, u0.w, acc[3]);
        acc[4] = fmaf(co, u1.x, acc[4]); acc[5] = fmaf(co, u1.y, acc[5]);
        acc[6] = fmaf(co, u1.z, acc[6]); acc[7] = fmaf(co, u1.w, acc[7]);
    }
    float4* op = (float4*)(g_gout + (size_t)n * HE + c0);
    op[0] = make_float4(acc[0], acc[1], acc[2], acc[3]);
    op[1] = make_float4(acc[4], acc[5], acc[6], acc[7]);
}

// ---------------- proj GEMM + elu + residual + LN (fused) ----------------
__global__ __launch_bounds__(256) void k_proj_ln(const float* __restrict__ B,
                                                 const float* __restrict__ pb,
                                                 const float* __restrict__ lg,
                                                 const float* __restrict__ lb) {
    __shared__ float As[64][65];
    __shared__ float Bs[64][65];
    __shared__ float r1[64][4], r2[64][4];
    __shared__ float smu[64], srs[64];
    int tid = threadIdx.x;
    int row0 = blockIdx.x * 64;
    int tx = tid & 15, ty = tid >> 4;
    float acc[4][4] = {};
    for (int kt = 0; kt < 4; kt++) {
#pragma unroll
        for (int i = 0; i < 16; i++) {
            int idx = tid + i * 256;
            int r = idx >> 6, k = idx & 63;
            int rr = row0 + r;
            As[r][k] = (rr < NT) ? g_gout[(size_t)rr * HE + kt * 64 + k] : 0.f;
            Bs[r][k] = B[(size_t)(kt * 64 + r) * 64 + k];
        }
        __syncthreads();
#pragma unroll
        for (int k = 0; k < 64; k++) {
            float a[4], bb[4];
#pragma unroll
            for (int i = 0; i < 4; i++) a[i] = As[ty * 4 + i][k];
#pragma unroll
            for (int j = 0; j < 4; j++) bb[j] = Bs[k][tx * 4 + j];
#pragma unroll
            for (int i = 0; i < 4; i++)
#pragma unroll
                for (int j = 0; j < 4; j++) acc[i][j] = fmaf(a[i], bb[j], acc[i][j]);
        }
        __syncthreads();
    }
    // stage upd = elu(acc + bias) into As
#pragma unroll
    for (int i = 0; i < 4; i++)
#pragma unroll
        for (int j = 0; j < 4; j++) {
            int c = tx * 4 + j;
            float u = acc[i][j] + pb[c];
            As[ty * 4 + i][c] = (u > 0.f) ? u : expm1f(u);
        }
    __syncthreads();
    // residual + row stats (4 threads per row, 16 cols each)
    {
        int row = tid >> 2, seg = tid & 3;
        int gr = row0 + row;
        bool valid = gr < NT;
        float s1 = 0.f, s2 = 0.f;
#pragma unroll
        for (int k = 0; k < 16; k++) {
            int c = seg * 16 + k;
            float hres = As[row][c] + (valid ? g_ht[(size_t)gr * 64 + c] : 0.f);
            As[row][c] = hres;
            s1 += hres;
            s2 += hres * hres;
        }
        r1[row][seg] = s1;
        r2[row][seg] = s2;
    }
    __syncthreads();
    if (tid < 64) {
        float mu = (r1[tid][0] + r1[tid][1] + r1[tid][2] + r1[tid][3]) * (1.f / 64.f);
        float ms = (r2[tid][0] + r2[tid][1] + r2[tid][2] + r2[tid][3]) * (1.f / 64.f);
        float var = ms - mu * mu;
        smu[tid] = mu;
        srs[tid] = rsqrtf(var + 1e-5f);
    }
    __syncthreads();
#pragma unroll
    for (int i = 0; i < 16; i++) {
        int idx = tid + i * 256;
        int r = idx >> 6, c = idx & 63;
        int gr = row0 + r;
        if (gr < NT)
            g_ht[(size_t)gr * 64 + c] = (As[r][c] - smu[r]) * srs[r] * __ldg(&lg[c]) + __ldg(&lb[c]);
    }
}

// ---------------- task head ----------------
__global__ __launch_bounds__(256) void k_taskhead(const float* __restrict__ W1,
                                                  const float* __restrict__ b1,
                                                  const float* __restrict__ W2,
                                                  const float* __restrict__ b2,
                                                  float* __restrict__ out) {
    __shared__ float sW1[64 * 32];
    __shared__ float sW2[32];
    __shared__ float sb1[32];
    int tid = threadIdx.x;
    for (int i = tid; i < 64 * 32; i += 256) sW1[i] = W1[i];
    if (tid < 32) { sW2[tid] = W2[tid]; sb1[tid] = b1[tid]; }
    __syncthreads();
    int n = blockIdx.x * 256 + tid;
    if (n >= NT) return;
    float row[64];
    const float4* rp = (const float4*)(g_ht + (size_t)n * 64);
#pragma unroll
    for (int i = 0; i < 16; i++) {
        float4 v = __ldg(rp + i);
        row[i * 4] = v.x; row[i * 4 + 1] = v.y; row[i * 4 + 2] = v.z; row[i * 4 + 3] = v.w;
    }
    float hid[32];
#pragma unroll
    for (int j = 0; j < 32; j++) hid[j] = sb1[j];
#pragma unroll 4
    for (int k = 0; k < 64; k++) {
        float rv = row[k];
#pragma unroll
        for (int j = 0; j < 32; j++) hid[j] = fmaf(rv, sW1[k * 32 + j], hid[j]);
    }
    float logit = __ldg(b2);
#pragma unroll
    for (int j = 0; j < 32; j++) logit = fmaf(fmaxf(hid[j], 0.f), sW2[j], logit);
    out[n] = logit;
}

// ---------------- pooling ----------------
__global__ void k_pool_task(const int* __restrict__ batch) {
    int c = threadIdx.x;
    int r0 = blockIdx.x * 512;
    int r1 = min(r0 + 512, NT);
    float acc = 0.f; int cg = -1; int cnt = 0;
    for (int r = r0; r < r1; r++) {
        int g = batch[r];
        if (g != cg) {
            if (cg >= 0) {
                atomicAdd(&g_tp[cg * 64 + c], acc);
                if (c == 0) atomicAdd(&g_cntt[cg], cnt);
            }
            cg = g; acc = 0.f; cnt = 0;
        }
        acc += g_ht[(size_t)r * 64 + c];
        cnt++;
    }
    if (cg >= 0) {
        atomicAdd(&g_tp[cg * 64 + c], acc);
        if (c == 0) atomicAdd(&g_cntt[cg], cnt);
    }
}

__global__ void k_pool_proc(const int* __restrict__ batch) {
    int c = threadIdx.x;
    float acc = 0.f; int cg = -1; int cnt = 0;
    for (int r = 0; r < NP; r++) {
        int g = batch[r];
        if (g != cg) {
            if (cg >= 0) {
                atomicAdd(&g_pp[cg * 64 + c], acc);
                if (c == 0) atomicAdd(&g_cntp[cg], cnt);
            }
            cg = g; acc = 0.f; cnt = 0;
        }
        acc += g_hp[r * 64 + c];
        cnt++;
    }
    if (cg >= 0) {
        atomicAdd(&g_pp[cg * 64 + c], acc);
        if (c == 0) atomicAdd(&g_cntp[cg], cnt);
    }
}

// ---------------- value head ----------------
__global__ void k_value(const float* __restrict__ W1, const float* __restrict__ b1,
                        const float* __restrict__ W2, const float* __restrict__ b2,
                        float* __restrict__ out) {
    __shared__ float ge[NG * 128];
    __shared__ float red[512];
    int t = threadIdx.x;
    for (int idx = t; idx < NG * 128; idx += 512) {
        int g = idx >> 7, k = idx & 127;
        float v;
        if (k < 64) v = g_tp[g * 64 + k] / fmaxf((float)g_cntt[g], 1.f);
        else        v = g_pp[g * 64 + (k - 64)] / fmaxf((float)g_cntp[g], 1.f);
        ge[idx] = v;
    }
    __syncthreads();
    int g = t >> 6, j = t & 63;
    float a = b1[j];
#pragma unroll 4
    for (int k = 0; k < 128; k++) a = fmaf(ge[g * 128 + k], W1[k * 64 + j], a);
    red[t] = fmaxf(a, 0.f) * W2[j];
    __syncthreads();
#pragma unroll
    for (int off = 32; off >= 1; off >>= 1) {
        if (j < off) red[t] += red[t + off];
        __syncthreads();
    }
    if (j == 0) out[NT + g] = red[t] + b2[0];
}

// ---------------- copy state outputs ----------------
__global__ void k_copyout(float* __restrict__ out) {
    int i = blockIdx.x * blockDim.x + threadIdx.x;
    int stride = gridDim.x * blockDim.x;
    const int OFF_HT = NT + NG;               // 50008
    const int OFF_HP = OFF_HT + NT * EMB;     // 3250008
    for (int k = i; k < NT * EMB; k += stride) out[OFF_HT + k] = g_ht[k];
    for (int k = i; k < NP * EMB; k += stride) out[OFF_HP + k] = g_hp[k];
}

// ---------------- launch ----------------
extern "C" void kernel_launch(void* const* d_in, const int* in_sizes, int n_in,
                              void* d_out, int out_size) {
    const float *x_task, *x_proc, *edge_attr, *W_task, *b_task, *W_proc, *b_proc;
    const float *gat_W, *gat_We, *att_src, *att_dst, *att_edge, *gat_b, *proj_W, *proj_b;
    const float *ln_g, *ln_b, *pt_W1, *pt_b1, *pt_W2, *pt_b2, *v_W1, *v_b1, *v_W2, *v_b2;
    const int *edge_index, *task_batch, *proc_batch;

    if (in_sizes[2] == 2 * NE) {  // setup_inputs dict order
        x_task = (const float*)d_in[0];  x_proc = (const float*)d_in[1];
        edge_index = (const int*)d_in[2]; edge_attr = (const float*)d_in[3];
        task_batch = (const int*)d_in[4]; proc_batch = (const int*)d_in[5];
        W_task = (const float*)d_in[6];  b_task = (const float*)d_in[7];
        W_proc = (const float*)d_in[8];  b_proc = (const float*)d_in[9];
        gat_W = (const float*)d_in[10];  gat_We = (const float*)d_in[11];
        att_src = (const float*)d_in[12]; att_dst = (const float*)d_in[13];
        att_edge = (const float*)d_in[14]; gat_b = (const float*)d_in[15];
        proj_W = (const float*)d_in[16]; proj_b = (const float*)d_in[17];
        ln_g = (const float*)d_in[18];   ln_b = (const float*)d_in[19];
        pt_W1 = (const float*)d_in[20];  pt_b1 = (const float*)d_in[21];
        pt_W2 = (const float*)d_in[22];  pt_b2 = (const float*)d_in[23];
        v_W1 = (const float*)d_in[24];   v_b1 = (const float*)d_in[25];
        v_W2 = (const float*)d_in[26];   v_b2 = (const float*)d_in[27];
    } else {  // reference() signature order
        x_task = (const float*)d_in[0];  x_proc = (const float*)d_in[1];
        edge_attr = (const float*)d_in[2];
        W_task = (const float*)d_in[3];  b_task = (const float*)d_in[4];
        W_proc = (const float*)d_in[5];  b_proc = (const float*)d_in[6];
        gat_W = (const float*)d_in[7];   gat_We = (const float*)d_in[8];
        att_src = (const float*)d_in[9]; att_dst = (const float*)d_in[10];
        att_edge = (const float*)d_in[11]; gat_b = (const float*)d_in[12];
        proj_W = (const float*)d_in[13]; proj_b = (const float*)d_in[14];
        ln_g = (const float*)d_in[15];   ln_b = (const float*)d_in[16];
        pt_W1 = (const float*)d_in[17];  pt_b1 = (const float*)d_in[18];
        pt_W2 = (const float*)d_in[19];  pt_b2 = (const float*)d_in[20];
        v_W1 = (const float*)d_in[21];   v_b1 = (const float*)d_in[22];
        v_W2 = (const float*)d_in[23];   v_b2 = (const float*)d_in[24];
        edge_index = (const int*)d_in[25];
        task_batch = (const int*)d_in[26]; proc_batch = (const int*)d_in[27];
    }
    float* out = (float*)d_out;
    const int* e_src = edge_index;
    const int* e_dst = edge_index + NE;

    k_init<<<128, 256>>>();
    k_meanea<<<256, 256>>>(edge_attr);
    k_hist<<<(NE + 255) / 256, 256>>>(e_dst);
    k_scan1<<<SCAN_B, 256>>>();
    k_scan2<<<1, 256>>>();
    k_scan3<<<SCAN_B, 256>>>();
    k_scatter<<<(NE + 255) / 256, 256>>>(e_src, e_dst, edge_attr);
    k_cvec<<<1, 128>>>(gat_We, att_edge);
    k_embed_task<<<NT / 4, dim3(64, 4)>>>(x_task, W_task, b_task);
    k_embed_proc<<<(NP * EMB + 255) / 256, 256>>>(x_proc, W_proc, b_proc);

    for (int l = 0; l < NL; l++) {
        k_gemm1<<<dim3((NT + 63) / 64, 4), 256>>>(gat_W + (size_t)l * EMB * HE,
                                                  att_src + l * H * EMB,
                                                  att_dst + l * H * EMB);
        k_agg<<<NT / 4, 128>>>(gat_b + l * HE, l);
        k_proj_ln<<<(NT + 63) / 64, 256>>>(proj_W + (size_t)l * HE * EMB,
                                           proj_b + l * EMB, ln_g + l * EMB, ln_b + l * EMB);
    }

    k_taskhead<<<(NT + 255) / 256, 256>>>(pt_W1, pt_b1, pt_W2, pt_b2, out);
    k_pool_task<<<(NT + 511) / 512, 64>>>(task_batch);
    k_pool_proc<<<1, 64>>>(proc_batch);
    k_value<<<1, 512>>>(v_W1, v_b1, v_W2, v_b2, out);
    k_copyout<<<2048, 256>>>(out);
}